// round 2
// baseline (speedup 1.0000x reference)
#include <cuda_runtime.h>

#define NBATCH 256
#define TLEN   256
#define DZ     32
#define DA     16
#define DU     8
#define KMIX   4
#define HID    64
#define G3     192   // 3*HID
#define SPAD   36    // row pad: float4-aligned, decent bank spread

// output segment offsets (floats); order: z, mu, Sig, a, A_t, B_t, C_t
#define OFF_Z   0LL
#define OFF_MU  2097152LL
#define OFF_SIG 4194304LL
#define OFF_A   71303168LL
#define OFF_AT  72351744LL
#define OFF_BT  139460608LL
#define OFF_CT  156237824LL

struct Smem {
    float A[DZ][SPAD];   // A_t
    float L[DZ][SPAD];   // cholesky factor (lower, upper zeroed)
    float G[DZ][SPAD];   // A_t @ L
    float S[DZ][SPAD];   // Sigma_t
    float Q[DZ][SPAD];
    float Ct[DA][SPAD];
    float Bt[DZ][DU];
    float mu[DZ];
    float mun[DZ];
    float h[HID];
    float z[DZ];
    float eps[DZ];
    float u[DU];
    float gh[G3];
    float alpha[KMIX];
};

// Warp 0 (32 lanes, lane = row): in-register Cholesky of sm.S -> sm.L,
// fused z = mu_next + L @ eps accumulated column-by-column.
__device__ __forceinline__ void chol32_warp(Smem& sm, int lane)
{
    float a[DZ];
#pragma unroll
    for (int k = 0; k < DZ; ++k) a[k] = sm.S[lane][k];
    float eps_own = sm.eps[lane];
    float zacc    = sm.mun[lane];
#pragma unroll
    for (int j = 0; j < DZ; ++j) {
        float d   = __shfl_sync(0xffffffffu, a[j], j);   // current diagonal
        float rs  = rsqrtf(d);
        float lij = a[j] * rs;                            // L[lane][j] (valid for lane>=j)
        a[j] = lij;
        // z accumulation (off the d-critical path)
        float ej = __shfl_sync(0xffffffffu, eps_own, j);
        if (lane >= j) zacc = fmaf(lij, ej, zacc);
        float lsq = lij * lij;
#pragma unroll
        for (int k = j + 1; k < DZ; ++k) {
            float lkj = __shfl_sync(0xffffffffu, lij, k); // L[k][j] from lane k
            if (k == lane) a[k] -= lsq;                   // own diag: no shfl dep
            else           a[k] = fmaf(-lij, lkj, a[k]);
        }
    }
#pragma unroll
    for (int k = 0; k < DZ; ++k) sm.L[lane][k] = (k <= lane) ? a[k] : 0.f;
    sm.z[lane] = zacc;
}

__global__ void __launch_bounds__(256, 2)
lgssm_kernel(const float* __restrict__ mu0,   const float* __restrict__ Sig0,
             const float* __restrict__ alpha0,const float* __restrict__ h0,
             const float* __restrict__ u_f,   const float* __restrict__ eps_g,
             const float* __restrict__ Abase, const float* __restrict__ Bbase,
             const float* __restrict__ Cbase, const float* __restrict__ Qm,
             const float* __restrict__ Wx,    const float* __restrict__ Wh,
             const float* __restrict__ bx,    const float* __restrict__ bh,
             const float* __restrict__ Wo,    const float* __restrict__ bo,
             float* __restrict__ out)
{
    __shared__ Smem sm;
    const int b    = blockIdx.x;
    const int tid  = threadIdx.x;
    const int lane = tid & 31;
    const int wid  = tid >> 5;
    const int i_row = tid >> 3;        // 0..31
    const int j0    = (tid & 7) * 4;   // 0,4,...,28

    // ---- init: load persistent state + Q + Sigma0
    if (tid < DZ)   sm.mu[tid]    = mu0[b * DZ + tid];
    if (tid < KMIX) sm.alpha[tid] = alpha0[b * KMIX + tid];
    if (tid >= 32 && tid < 96) sm.h[tid - 32] = h0[b * HID + (tid - 32)];
    {
        float4 q4 = *(const float4*)(Qm + i_row * DZ + j0);
        *(float4*)&sm.Q[i_row][j0] = q4;
        float4 s4 = *(const float4*)(Sig0 + (long long)b * DZ * DZ + i_row * DZ + j0);
        *(float4*)&sm.S[i_row][j0] = s4;
    }
    __syncthreads();
    if (wid == 0) chol32_warp(sm, lane);   // L0 = chol(Sigma0); z garbage (unused)
    __syncthreads();

    const long long bt0 = (long long)b * TLEN;

    for (int t = 0; t < TLEN; ++t) {
        const long long bt = bt0 + t;

        // ================= stage A: mixtures A_t/B_t/C_t, load u/eps ===========
        {
            float al0 = sm.alpha[0], al1 = sm.alpha[1], al2 = sm.alpha[2], al3 = sm.alpha[3];
            // A_t: 4 consecutive elems per thread (flat idx = 4*tid)
            const float4* A4 = (const float4*)Abase;
            float4 x0 = __ldg(&A4[tid]),        x1 = __ldg(&A4[256 + tid]);
            float4 x2 = __ldg(&A4[512 + tid]),  x3 = __ldg(&A4[768 + tid]);
            float4 at;
            at.x = al0*x0.x + al1*x1.x + al2*x2.x + al3*x3.x;
            at.y = al0*x0.y + al1*x1.y + al2*x2.y + al3*x3.y;
            at.z = al0*x0.z + al1*x1.z + al2*x2.z + al3*x3.z;
            at.w = al0*x0.w + al1*x1.w + al2*x2.w + al3*x3.w;
            *(float4*)&sm.A[i_row][j0] = at;
            *(float4*)(out + OFF_AT + bt * 1024 + tid * 4) = at;
            // B_t: one elem per thread
            float bv = al0*__ldg(&Bbase[tid])       + al1*__ldg(&Bbase[256 + tid])
                     + al2*__ldg(&Bbase[512 + tid]) + al3*__ldg(&Bbase[768 + tid]);
            ((float*)sm.Bt)[tid] = bv;
            out[OFF_BT + bt * 256 + tid] = bv;
            // C_t: two elems per thread (flat idx = 2*tid)
            const float2* C2 = (const float2*)Cbase;
            float2 c0 = __ldg(&C2[tid]),       c1 = __ldg(&C2[256 + tid]);
            float2 c2 = __ldg(&C2[512 + tid]), c3 = __ldg(&C2[768 + tid]);
            float2 ct;
            ct.x = al0*c0.x + al1*c1.x + al2*c2.x + al3*c3.x;
            ct.y = al0*c0.y + al1*c1.y + al2*c2.y + al3*c3.y;
            int crow = (2 * tid) >> 5, ccol = (2 * tid) & 31;
            *(float2*)&sm.Ct[crow][ccol] = ct;
            *(float2*)(out + OFF_CT + bt * 512 + tid * 2) = ct;
            // u_t, eps_t
            if (tid < DZ)                 sm.eps[tid] = eps_g[bt * DZ + tid];
            else if (tid < DZ + DU)       sm.u[tid - DZ] = u_f[bt * DU + (tid - DZ)];
        }
        __syncthreads();

        // ================= stage B: G = A_t @ L ; mu_next =====================
        {
            float g0 = 0.f, g1 = 0.f, g2 = 0.f, g3 = 0.f;
#pragma unroll
            for (int k0 = 0; k0 < DZ; k0 += 4) {
                float4 ar = *(const float4*)&sm.A[i_row][k0];
                float4 l0 = *(const float4*)&sm.L[k0 + 0][j0];
                float4 l1 = *(const float4*)&sm.L[k0 + 1][j0];
                float4 l2 = *(const float4*)&sm.L[k0 + 2][j0];
                float4 l3 = *(const float4*)&sm.L[k0 + 3][j0];
                g0 = fmaf(ar.x, l0.x, fmaf(ar.y, l1.x, fmaf(ar.z, l2.x, fmaf(ar.w, l3.x, g0))));
                g1 = fmaf(ar.x, l0.y, fmaf(ar.y, l1.y, fmaf(ar.z, l2.y, fmaf(ar.w, l3.y, g1))));
                g2 = fmaf(ar.x, l0.z, fmaf(ar.y, l1.z, fmaf(ar.z, l2.z, fmaf(ar.w, l3.z, g2))));
                g3 = fmaf(ar.x, l0.w, fmaf(ar.y, l1.w, fmaf(ar.z, l2.w, fmaf(ar.w, l3.w, g3))));
            }
            *(float4*)&sm.G[i_row][j0] = make_float4(g0, g1, g2, g3);
            if (tid < DZ) {   // mu_next = A_t mu + B_t u
                float acc = 0.f;
#pragma unroll
                for (int k = 0; k < DZ; ++k) acc = fmaf(sm.A[tid][k], sm.mu[k], acc);
#pragma unroll
                for (int k = 0; k < DU; ++k) acc = fmaf(sm.Bt[tid][k], sm.u[k], acc);
                sm.mun[tid] = acc;
                out[OFF_MU + bt * DZ + tid] = acc;
            }
        }
        __syncthreads();

        // ================= stage C: S = G G^T + Q =============================
        {
            float s0 = 0.f, s1 = 0.f, s2 = 0.f, s3 = 0.f;
#pragma unroll
            for (int k0 = 0; k0 < DZ; k0 += 4) {
                float4 gi = *(const float4*)&sm.G[i_row][k0];
                float4 q0 = *(const float4*)&sm.G[j0 + 0][k0];
                float4 q1 = *(const float4*)&sm.G[j0 + 1][k0];
                float4 q2 = *(const float4*)&sm.G[j0 + 2][k0];
                float4 q3 = *(const float4*)&sm.G[j0 + 3][k0];
                s0 = fmaf(gi.x, q0.x, fmaf(gi.y, q0.y, fmaf(gi.z, q0.z, fmaf(gi.w, q0.w, s0))));
                s1 = fmaf(gi.x, q1.x, fmaf(gi.y, q1.y, fmaf(gi.z, q1.z, fmaf(gi.w, q1.w, s1))));
                s2 = fmaf(gi.x, q2.x, fmaf(gi.y, q2.y, fmaf(gi.z, q2.z, fmaf(gi.w, q2.w, s2))));
                s3 = fmaf(gi.x, q3.x, fmaf(gi.y, q3.y, fmaf(gi.z, q3.z, fmaf(gi.w, q3.w, s3))));
            }
            float4 qq = *(const float4*)&sm.Q[i_row][j0];
            *(float4*)&sm.S[i_row][j0] = make_float4(s0 + qq.x, s1 + qq.y, s2 + qq.z, s3 + qq.w);
        }
        __syncthreads();

        // ===== stage D: warp0 chol (+fused z); warps1-7 store Sig + compute gh =
        if (wid == 0) {
            chol32_warp(sm, lane);
        } else {
            int c = tid - 32;                       // 0..223 over 256 float4 chunks
            {
                int ci = c >> 3, cj = (c & 7) * 4;
                float4 v = *(const float4*)&sm.S[ci][cj];
                *(float4*)(out + OFF_SIG + bt * 1024 + c * 4) = v;
            }
            if (c < 32) {
                int c2 = c + 224;
                int ci = c2 >> 3, cj = (c2 & 7) * 4;
                float4 v = *(const float4*)&sm.S[ci][cj];
                *(float4*)(out + OFF_SIG + bt * 1024 + c2 * 4) = v;
            }
            if (tid < 32 + G3) {                    // gh = h @ Wh + bh (indep of z)
                int g = tid - 32;
                float acc = __ldg(&bh[g]);
#pragma unroll 8
                for (int hh = 0; hh < HID; ++hh)
                    acc = fmaf(sm.h[hh], __ldg(&Wh[hh * G3 + g]), acc);
                sm.gh[g] = acc;
            }
        }
        __syncthreads();

        // ================= stage F: z/a_t outputs, GRU update =================
        if (tid < DZ) out[OFF_Z + bt * DZ + tid] = sm.z[tid];
        if (tid >= 224 && tid < 224 + DA) {         // a_t = C_t z
            int r = tid - 224;
            float acc = 0.f;
#pragma unroll
            for (int k = 0; k < DZ; ++k) acc = fmaf(sm.Ct[r][k], sm.z[k], acc);
            out[OFF_A + bt * DA + r] = acc;
        }
        if (tid >= 64 && tid < 128) {               // GRU, one hidden unit per thread
            int hh = tid - 64;
            float xr = __ldg(&bx[hh]), xz = __ldg(&bx[64 + hh]), xn = __ldg(&bx[128 + hh]);
#pragma unroll
            for (int k = 0; k < DZ; ++k) {
                float zk = sm.z[k];
                xr = fmaf(zk, __ldg(&Wx[k * G3 + hh]),       xr);
                xz = fmaf(zk, __ldg(&Wx[k * G3 + 64 + hh]),  xz);
                xn = fmaf(zk, __ldg(&Wx[k * G3 + 128 + hh]), xn);
            }
            float hr = sm.gh[hh], hz = sm.gh[64 + hh], hn = sm.gh[128 + hh];
            float r  = 1.f / (1.f + __expf(-(xr + hr)));
            float zg = 1.f / (1.f + __expf(-(xz + hz)));
            float n  = tanhf(xn + r * hn);
            float hnew = (1.f - zg) * n + zg * sm.h[hh];
            sm.h[hh] = hnew;                        // only this thread reads/writes hh
        }
        if (tid >= 128 && tid < 160) sm.mu[tid - 128] = sm.mun[tid - 128];
        __syncthreads();

        // ================= stage G: alpha = softmax(h @ Wo + bo) ==============
        if (wid == 0) {
            int k = lane >> 3;      // output index 0..3
            int p = lane & 7;       // partial index
            float acc = 0.f;
#pragma unroll
            for (int q = 0; q < 8; ++q) {
                int hh = p * 8 + q;
                acc = fmaf(sm.h[hh], __ldg(&Wo[hh * KMIX + k]), acc);
            }
            acc += __shfl_xor_sync(0xffffffffu, acc, 4);
            acc += __shfl_xor_sync(0xffffffffu, acc, 2);
            acc += __shfl_xor_sync(0xffffffffu, acc, 1);
            float o = acc + __ldg(&bo[k]);
            float m = fmaxf(o,  __shfl_xor_sync(0xffffffffu, o, 8));
            m       = fmaxf(m,  __shfl_xor_sync(0xffffffffu, m, 16));
            float e = __expf(o - m);
            float s = e + __shfl_xor_sync(0xffffffffu, e, 8);
            s       = s + __shfl_xor_sync(0xffffffffu, s, 16);
            if (p == 0) sm.alpha[k] = e / s;
        }
        __syncthreads();
    }
}

extern "C" void kernel_launch(void* const* d_in, const int* in_sizes, int n_in,
                              void* d_out, int out_size)
{
    lgssm_kernel<<<NBATCH, 256>>>(
        (const float*)d_in[0],  (const float*)d_in[1],  (const float*)d_in[2],
        (const float*)d_in[3],  (const float*)d_in[4],  (const float*)d_in[5],
        (const float*)d_in[6],  (const float*)d_in[7],  (const float*)d_in[8],
        (const float*)d_in[9],  (const float*)d_in[10], (const float*)d_in[11],
        (const float*)d_in[12], (const float*)d_in[13], (const float*)d_in[14],
        (const float*)d_in[15], (float*)d_out);
}